// round 10
// baseline (speedup 1.0000x reference)
#include <cuda_runtime.h>
#include <cuda_fp16.h>

#define RES   256
#define FEAT  32
#define NPTS  524288
#define NBA   32
#define NBINS (NBA * NBA * NBA)   // 32768

// Pair-interleaved fp16 planes: cell (y,x) -> 128B block of half2(f(x,c), f(x+1,c))
__device__ __half2  g_pi[3][RES * RES * FEAT];   // 25 MB
__device__ unsigned g_binid[NPTS];
__device__ unsigned g_count[NBINS];              // zero-init; re-zeroed by scan
__device__ unsigned g_offset[NBINS];
__device__ float4   g_sdata[NPTS * 2];

// ---------------- plane interleave: (C,H,W) fp32 -> (H,W,C) half2 x-pairs ----------------
__global__ void interleave_kernel(const float* __restrict__ p0,
                                  const float* __restrict__ p1,
                                  const float* __restrict__ p2) {
    __shared__ float srow[FEAT][RES + 1];
    const float* src = (blockIdx.y == 0) ? p0 : (blockIdx.y == 1 ? p1 : p2);
    __half2* dst = g_pi[blockIdx.y];
    const int y = blockIdx.x;
    const int t = threadIdx.x;

    #pragma unroll
    for (int c = 0; c < FEAT; c++)
        srow[c][t] = src[c * (RES * RES) + y * RES + t];
    __syncthreads();

    #pragma unroll
    for (int i = t; i < RES * FEAT; i += 256) {
        const int x = i >> 5;
        const int c = i & 31;
        const float a = srow[c][x];
        const float b = srow[c][(x + 1 < RES) ? x + 1 : RES - 1];
        dst[(y * RES + x) * FEAT + c] = __floats2half2_rn(a, b);
    }
}

// ---------------- Morton counting sort ----------------
__device__ __forceinline__ unsigned spread3(unsigned v) {
    unsigned r = (v & 1u);
    r |= (v & 2u)  << 2;
    r |= (v & 4u)  << 4;
    r |= (v & 8u)  << 6;
    r |= (v & 16u) << 8;
    return r;
}

__global__ void bin_kernel(const float* __restrict__ pts) {
    int p = blockIdx.x * blockDim.x + threadIdx.x;
    if (p >= NPTS) return;
    const float x = pts[p * 3 + 0];
    const float y = pts[p * 3 + 1];
    const float z = pts[p * 3 + 2];
    const float k = (float)NBA / 2.6f;
    int ix = min(NBA - 1, max(0, (int)((x + 1.3f) * k)));
    int iy = min(NBA - 1, max(0, (int)((y + 1.3f) * k)));
    int iz = min(NBA - 1, max(0, (int)((z + 1.3f) * k)));
    unsigned code = spread3(ix) | (spread3(iy) << 1) | (spread3(iz) << 2);
    g_binid[p] = code;
    atomicAdd(&g_count[code], 1u);
}

// single-block exclusive scan of g_count -> g_offset (absolute); re-zeroes g_count
__global__ void scan_kernel() {
    __shared__ unsigned sh[1024];
    const int t = threadIdx.x;        // 1024 threads, 32 bins each
    unsigned local[32];
    unsigned sum = 0;
    #pragma unroll
    for (int k = 0; k < 32; k++) {
        const int idx = t * 32 + k;
        const unsigned v = g_count[idx];
        g_count[idx] = 0;
        local[k] = sum;
        sum += v;
    }
    sh[t] = sum;
    __syncthreads();
    #pragma unroll
    for (int d = 1; d < 1024; d <<= 1) {
        unsigned add = (t >= d) ? sh[t - d] : 0u;
        __syncthreads();
        sh[t] += add;
        __syncthreads();
    }
    const unsigned base = sh[t] - sum;   // block-exclusive for this thread
    #pragma unroll
    for (int k = 0; k < 32; k++)
        g_offset[t * 32 + k] = base + local[k];
}

__global__ void scatter_kernel(const float* __restrict__ pts,
                               const float* __restrict__ scales,
                               const float* __restrict__ aabb) {
    int p = blockIdx.x * blockDim.x + threadIdx.x;
    if (p >= NPTS) return;
    const unsigned bin = g_binid[p];
    const unsigned pos = atomicAdd(&g_offset[bin], 1u);

    const float a00 = aabb[0], a01 = aabb[1], a02 = aabb[2];
    const float a10 = aabb[3], a11 = aabb[4], a12 = aabb[5];
    const float n0 = (pts[p * 3 + 0] - a00) * (2.0f / (a10 - a00)) - 1.0f;
    const float n1 = (pts[p * 3 + 1] - a01) * (2.0f / (a11 - a01)) - 1.0f;
    const float n2 = (pts[p * 3 + 2] - a02) * (2.0f / (a12 - a02)) - 1.0f;

    g_sdata[pos * 2 + 0] = make_float4(n0, n1, n2, scales[p * 3 + 0]);
    g_sdata[pos * 2 + 1] = make_float4(scales[p * 3 + 1], scales[p * 3 + 2],
                                       __int_as_float(p), 0.0f);
}

// ---------------- main sampling kernel ----------------
__host__ __device__ constexpr int SIX(int s) {
    constexpr int t[13] = {2, 0, 1, 3, 4, 2, 2, 2, 2, 3, 3, 1, 1};
    return t[s];
}
__host__ __device__ constexpr int SIY(int s) {
    constexpr int t[13] = {2, 2, 2, 2, 2, 0, 1, 3, 4, 3, 1, 3, 1};
    return t[s];
}

// 8 lanes per point (4 channels each), 4 sorted points per warp.
// 4-sample fp16 chains with 2+2 staged loads (low reg pressure), occupancy 4.
__global__ void __launch_bounds__(256, 4) sample_kernel(float* __restrict__ out)
{
    const int tid  = blockIdx.x * blockDim.x + threadIdx.x;
    const int lane = tid & 31;
    const int grp  = lane >> 3;
    const int cl   = lane & 7;
    const int i    = (tid >> 5) * 4 + grp;

    const float4 d0 = g_sdata[i * 2 + 0];
    const float4 d1 = g_sdata[i * 2 + 1];
    const float n[3] = { d0.x, d0.y, d0.z };
    const float s[3] = { d0.w, d1.x, d1.y };
    const int   orig = __float_as_int(d1.z);

    const int qidx[3] = {0, 0, 1};
    const int ridx[3] = {1, 2, 2};

    float res[4];
    #pragma unroll
    for (int j = 0; j < 4; j++) res[j] = 1.0f;

    #pragma unroll
    for (int pl = 0; pl < 3; pl++) {
        const float bx = n[qidx[pl]];
        const float by = n[ridx[pl]];
        const float sx = s[qidx[pl]];
        const float sy = s[ridx[pl]];
        const uint4* __restrict__ base = ((const uint4*)g_pi[pl]) + cl;

        float xw[5], yw[5];
        int   xo[5], yo0[5], yo1[5];
        #pragma unroll
        for (int k = 0; k < 5; k++) {
            const float m = (float)(k - 2) * 0.5f;

            const float gx = fmaf(sx, m, bx);
            float cx = fminf(fmaxf(fmaf(gx, 127.5f, 127.5f), 0.0f), 255.0f);
            const float x0f = floorf(cx);
            xw[k] = cx - x0f;
            xo[k] = (int)x0f * 8;

            const float gy = fmaf(sy, m, by);
            float cy = fminf(fmaxf(fmaf(gy, 127.5f, 127.5f), 0.0f), 255.0f);
            const float y0f = floorf(cy);
            yw[k] = cy - y0f;
            const int y0 = (int)y0f;
            yo0[k] = y0 * (RES * 8);
            yo1[k] = min(y0 + 1, RES - 1) * (RES * 8);
        }

        float accL[4], accH[4];
        #pragma unroll
        for (int j = 0; j < 4; j++) { accL[j] = 0.0f; accH[j] = 0.0f; }

        #define LOADQ(smp, Q0, Q1)                                            \
            { const int ax_ = SIX(smp); const int ay_ = SIY(smp);             \
              Q0 = base[yo0[ay_] + xo[ax_]];                                  \
              Q1 = base[yo1[ay_] + xo[ax_]]; }

        #define WPAIR(smp, WP0, WP1)                                          \
            { const float wx_ = xw[SIX(smp)];                                 \
              const float wy_ = yw[SIY(smp)];                                 \
              const float w11_ = wx_ * wy_;                                   \
              WP0 = __floats2half2_rn(1.0f - wx_ - (wy_ - w11_), wx_ - w11_); \
              WP1 = __floats2half2_rn(wy_ - w11_, w11_); }

        #define H2AT(Q, j) (*reinterpret_cast<const __half2*>(&(&(Q).x)[j]))

        // sample 0 alone, flushed
        {
            uint4 q0, q1;
            LOADQ(0, q0, q1);
            __half2 wp0, wp1;
            WPAIR(0, wp0, wp1);
            #pragma unroll
            for (int j = 0; j < 4; j++) {
                __half2 t = __hmul2(H2AT(q0, j), wp0);
                t = __hfma2(H2AT(q1, j), wp1, t);
                const float2 v = __half22float2(t);
                accL[j] += v.x; accH[j] += v.y;
            }
        }

        // 3 groups of 4 samples: fp16 chain (8 terms), loads staged 2+2.
        // Chain order identical to R9 -> bitwise-identical rounding.
        #pragma unroll
        for (int g = 0; g < 3; g++) {
            const int sA = 1 + g * 4, sB = 2 + g * 4, sC = 3 + g * 4, sD = 4 + g * 4;
            __half2 t0, t1, t2, t3;
            {
                uint4 qa0, qa1, qb0, qb1;
                LOADQ(sA, qa0, qa1);
                LOADQ(sB, qb0, qb1);
                __half2 wa0, wa1, wb0, wb1;
                WPAIR(sA, wa0, wa1);
                WPAIR(sB, wb0, wb1);
                t0 = __hmul2(H2AT(qa0, 0), wa0);
                t1 = __hmul2(H2AT(qa0, 1), wa0);
                t2 = __hmul2(H2AT(qa0, 2), wa0);
                t3 = __hmul2(H2AT(qa0, 3), wa0);
                t0 = __hfma2(H2AT(qa1, 0), wa1, t0);
                t1 = __hfma2(H2AT(qa1, 1), wa1, t1);
                t2 = __hfma2(H2AT(qa1, 2), wa1, t2);
                t3 = __hfma2(H2AT(qa1, 3), wa1, t3);
                t0 = __hfma2(H2AT(qb0, 0), wb0, t0);
                t1 = __hfma2(H2AT(qb0, 1), wb0, t1);
                t2 = __hfma2(H2AT(qb0, 2), wb0, t2);
                t3 = __hfma2(H2AT(qb0, 3), wb0, t3);
                t0 = __hfma2(H2AT(qb1, 0), wb1, t0);
                t1 = __hfma2(H2AT(qb1, 1), wb1, t1);
                t2 = __hfma2(H2AT(qb1, 2), wb1, t2);
                t3 = __hfma2(H2AT(qb1, 3), wb1, t3);
            }
            {
                uint4 qc0, qc1, qd0, qd1;
                LOADQ(sC, qc0, qc1);
                LOADQ(sD, qd0, qd1);
                __half2 wc0, wc1, wd0, wd1;
                WPAIR(sC, wc0, wc1);
                WPAIR(sD, wd0, wd1);
                t0 = __hfma2(H2AT(qc0, 0), wc0, t0);
                t1 = __hfma2(H2AT(qc0, 1), wc0, t1);
                t2 = __hfma2(H2AT(qc0, 2), wc0, t2);
                t3 = __hfma2(H2AT(qc0, 3), wc0, t3);
                t0 = __hfma2(H2AT(qc1, 0), wc1, t0);
                t1 = __hfma2(H2AT(qc1, 1), wc1, t1);
                t2 = __hfma2(H2AT(qc1, 2), wc1, t2);
                t3 = __hfma2(H2AT(qc1, 3), wc1, t3);
                t0 = __hfma2(H2AT(qd0, 0), wd0, t0);
                t1 = __hfma2(H2AT(qd0, 1), wd0, t1);
                t2 = __hfma2(H2AT(qd0, 2), wd0, t2);
                t3 = __hfma2(H2AT(qd0, 3), wd0, t3);
                t0 = __hfma2(H2AT(qd1, 0), wd1, t0);
                t1 = __hfma2(H2AT(qd1, 1), wd1, t1);
                t2 = __hfma2(H2AT(qd1, 2), wd1, t2);
                t3 = __hfma2(H2AT(qd1, 3), wd1, t3);
            }
            const float2 v0 = __half22float2(t0);
            const float2 v1 = __half22float2(t1);
            const float2 v2 = __half22float2(t2);
            const float2 v3 = __half22float2(t3);
            accL[0] += v0.x; accH[0] += v0.y;
            accL[1] += v1.x; accH[1] += v1.y;
            accL[2] += v2.x; accH[2] += v2.y;
            accL[3] += v3.x; accH[3] += v3.y;
        }
        #undef LOADQ
        #undef WPAIR
        #undef H2AT

        const float inv13 = 1.0f / 13.0f;
        #pragma unroll
        for (int j = 0; j < 4; j++)
            res[j] *= (accL[j] + accH[j]) * inv13;
    }

    float4 o;
    o.x = res[0]; o.y = res[1]; o.z = res[2]; o.w = res[3];
    ((float4*)out)[orig * 8 + cl] = o;
}

extern "C" void kernel_launch(void* const* d_in, const int* in_sizes, int n_in,
                              void* d_out, int out_size) {
    (void)in_sizes; (void)n_in; (void)out_size;
    const float* pts    = (const float*)d_in[0];
    const float* scales = (const float*)d_in[2];
    const float* p0     = (const float*)d_in[3];
    const float* p1     = (const float*)d_in[4];
    const float* p2     = (const float*)d_in[5];
    const float* aabb   = (const float*)d_in[6];
    float* out          = (float*)d_out;

    interleave_kernel<<<dim3(RES, 3), 256>>>(p0, p1, p2);
    bin_kernel<<<NPTS / 256, 256>>>(pts);
    scan_kernel<<<1, 1024>>>();
    scatter_kernel<<<NPTS / 256, 256>>>(pts, scales, aabb);
    sample_kernel<<<(NPTS * 8) / 256, 256>>>(out);
}

// round 11
// speedup vs baseline: 1.0239x; 1.0239x over previous
#include <cuda_runtime.h>
#include <cuda_fp16.h>

#define RES   256
#define FEAT  32
#define NPTS  524288
#define NBA   32
#define NBINS (NBA * NBA * NBA)   // 32768

// Pair-interleaved fp16 planes: cell (y,x) -> 128B block of half2(f(x,c), f(x+1,c))
__device__ __half2  g_pi[3][RES * RES * FEAT];   // 25 MB
__device__ unsigned g_binid[NPTS];
__device__ unsigned g_count[NBINS];              // zero-init; re-zeroed by scan
__device__ unsigned g_offset[NBINS];
__device__ float4   g_sdata[NPTS * 2];

__device__ __forceinline__ unsigned spread3(unsigned v) {
    unsigned r = (v & 1u);
    r |= (v & 2u)  << 2;
    r |= (v & 4u)  << 4;
    r |= (v & 8u)  << 6;
    r |= (v & 16u) << 8;
    return r;
}

// ---------------- fused prep: plane interleave (blocks 0..767) + binning (768..) ----
__global__ void prep_kernel(const float* __restrict__ p0,
                            const float* __restrict__ p1,
                            const float* __restrict__ p2,
                            const float* __restrict__ pts) {
    __shared__ float srow[FEAT][RES + 1];
    const int bid = blockIdx.x;
    const int t   = threadIdx.x;

    if (bid < 768) {
        // interleave: (C,H,W) fp32 -> (H,W,C) half2 x-pairs
        const int plane = bid >> 8;
        const int y     = bid & 255;
        const float* src = (plane == 0) ? p0 : (plane == 1 ? p1 : p2);
        __half2* dst = g_pi[plane];

        #pragma unroll
        for (int c = 0; c < FEAT; c++)
            srow[c][t] = src[c * (RES * RES) + y * RES + t];
        __syncthreads();

        #pragma unroll
        for (int i = t; i < RES * FEAT; i += 256) {
            const int x = i >> 5;
            const int c = i & 31;
            const float a = srow[c][x];
            const float b = srow[c][(x + 1 < RES) ? x + 1 : RES - 1];
            dst[(y * RES + x) * FEAT + c] = __floats2half2_rn(a, b);
        }
    } else {
        // binning
        const int p = (bid - 768) * 256 + t;
        if (p < NPTS) {
            const float x = pts[p * 3 + 0];
            const float y = pts[p * 3 + 1];
            const float z = pts[p * 3 + 2];
            const float k = (float)NBA / 2.6f;
            int ix = min(NBA - 1, max(0, (int)((x + 1.3f) * k)));
            int iy = min(NBA - 1, max(0, (int)((y + 1.3f) * k)));
            int iz = min(NBA - 1, max(0, (int)((z + 1.3f) * k)));
            unsigned code = spread3(ix) | (spread3(iy) << 1) | (spread3(iz) << 2);
            g_binid[p] = code;
            atomicAdd(&g_count[code], 1u);
        }
    }
}

// single-block exclusive scan of g_count -> g_offset (absolute); re-zeroes g_count
__global__ void scan_kernel() {
    __shared__ unsigned sh[1024];
    const int t = threadIdx.x;        // 1024 threads, 32 bins each
    unsigned local[32];
    unsigned sum = 0;
    #pragma unroll
    for (int k = 0; k < 32; k++) {
        const int idx = t * 32 + k;
        const unsigned v = g_count[idx];
        g_count[idx] = 0;
        local[k] = sum;
        sum += v;
    }
    sh[t] = sum;
    __syncthreads();
    #pragma unroll
    for (int d = 1; d < 1024; d <<= 1) {
        unsigned add = (t >= d) ? sh[t - d] : 0u;
        __syncthreads();
        sh[t] += add;
        __syncthreads();
    }
    const unsigned base = sh[t] - sum;
    #pragma unroll
    for (int k = 0; k < 32; k++)
        g_offset[t * 32 + k] = base + local[k];
}

__global__ void scatter_kernel(const float* __restrict__ pts,
                               const float* __restrict__ scales,
                               const float* __restrict__ aabb) {
    int p = blockIdx.x * blockDim.x + threadIdx.x;
    if (p >= NPTS) return;
    const unsigned bin = g_binid[p];
    const unsigned pos = atomicAdd(&g_offset[bin], 1u);

    const float a00 = aabb[0], a01 = aabb[1], a02 = aabb[2];
    const float a10 = aabb[3], a11 = aabb[4], a12 = aabb[5];
    const float n0 = (pts[p * 3 + 0] - a00) * (2.0f / (a10 - a00)) - 1.0f;
    const float n1 = (pts[p * 3 + 1] - a01) * (2.0f / (a11 - a01)) - 1.0f;
    const float n2 = (pts[p * 3 + 2] - a02) * (2.0f / (a12 - a02)) - 1.0f;

    g_sdata[pos * 2 + 0] = make_float4(n0, n1, n2, scales[p * 3 + 0]);
    g_sdata[pos * 2 + 1] = make_float4(scales[p * 3 + 1], scales[p * 3 + 2],
                                       __int_as_float(p), 0.0f);
}

// ---------------- main sampling kernel (exact R9 arithmetic) ----------------
__host__ __device__ constexpr int SIX(int s) {
    constexpr int t[13] = {2, 0, 1, 3, 4, 2, 2, 2, 2, 3, 3, 1, 1};
    return t[s];
}
__host__ __device__ constexpr int SIY(int s) {
    constexpr int t[13] = {2, 2, 2, 2, 2, 0, 1, 3, 4, 3, 1, 3, 1};
    return t[s];
}

__global__ void __launch_bounds__(256, 3) sample_kernel(float* __restrict__ out)
{
    const int tid  = blockIdx.x * blockDim.x + threadIdx.x;
    const int lane = tid & 31;
    const int grp  = lane >> 3;
    const int cl   = lane & 7;
    const int i    = (tid >> 5) * 4 + grp;

    const float4 d0 = g_sdata[i * 2 + 0];
    const float4 d1 = g_sdata[i * 2 + 1];
    const float n[3] = { d0.x, d0.y, d0.z };
    const float s[3] = { d0.w, d1.x, d1.y };
    const int   orig = __float_as_int(d1.z);

    const int qidx[3] = {0, 0, 1};
    const int ridx[3] = {1, 2, 2};

    float res[4];
    #pragma unroll
    for (int j = 0; j < 4; j++) res[j] = 1.0f;

    #pragma unroll
    for (int pl = 0; pl < 3; pl++) {
        const float bx = n[qidx[pl]];
        const float by = n[ridx[pl]];
        const float sx = s[qidx[pl]];
        const float sy = s[ridx[pl]];
        const uint4* __restrict__ base = ((const uint4*)g_pi[pl]) + cl;

        float xw[5], yw[5];
        int   xo[5], yo0[5], yo1[5];
        #pragma unroll
        for (int k = 0; k < 5; k++) {
            const float m = (float)(k - 2) * 0.5f;

            const float gx = fmaf(sx, m, bx);
            float cx = fminf(fmaxf(fmaf(gx, 127.5f, 127.5f), 0.0f), 255.0f);
            const float x0f = floorf(cx);
            xw[k] = cx - x0f;
            xo[k] = (int)x0f * 8;

            const float gy = fmaf(sy, m, by);
            float cy = fminf(fmaxf(fmaf(gy, 127.5f, 127.5f), 0.0f), 255.0f);
            const float y0f = floorf(cy);
            yw[k] = cy - y0f;
            const int y0 = (int)y0f;
            yo0[k] = y0 * (RES * 8);
            yo1[k] = min(y0 + 1, RES - 1) * (RES * 8);
        }

        float accL[4], accH[4];
        #pragma unroll
        for (int j = 0; j < 4; j++) { accL[j] = 0.0f; accH[j] = 0.0f; }

        #define LOADQ(smp, Q0, Q1)                                            \
            { const int ax_ = SIX(smp); const int ay_ = SIY(smp);             \
              Q0 = base[yo0[ay_] + xo[ax_]];                                  \
              Q1 = base[yo1[ay_] + xo[ax_]]; }

        #define WPAIR(smp, WP0, WP1)                                          \
            { const float wx_ = xw[SIX(smp)];                                 \
              const float wy_ = yw[SIY(smp)];                                 \
              const float w11_ = wx_ * wy_;                                   \
              WP0 = __floats2half2_rn(1.0f - wx_ - (wy_ - w11_), wx_ - w11_); \
              WP1 = __floats2half2_rn(wy_ - w11_, w11_); }

        #define H2AT(Q, j) (*reinterpret_cast<const __half2*>(&(&(Q).x)[j]))

        // sample 0 alone, flushed
        {
            uint4 q0, q1;
            LOADQ(0, q0, q1);
            __half2 wp0, wp1;
            WPAIR(0, wp0, wp1);
            #pragma unroll
            for (int j = 0; j < 4; j++) {
                __half2 t = __hmul2(H2AT(q0, j), wp0);
                t = __hfma2(H2AT(q1, j), wp1, t);
                const float2 v = __half22float2(t);
                accL[j] += v.x; accH[j] += v.y;
            }
        }

        // 3 groups of 4 samples: fp16 chain (8 terms), single flush
        #pragma unroll
        for (int g = 0; g < 3; g++) {
            const int sA = 1 + g * 4, sB = 2 + g * 4, sC = 3 + g * 4, sD = 4 + g * 4;
            uint4 qa0, qa1, qb0, qb1, qc0, qc1, qd0, qd1;
            LOADQ(sA, qa0, qa1);
            LOADQ(sB, qb0, qb1);
            LOADQ(sC, qc0, qc1);
            LOADQ(sD, qd0, qd1);

            __half2 wa0, wa1, wb0, wb1, wc0, wc1, wd0, wd1;
            WPAIR(sA, wa0, wa1);
            WPAIR(sB, wb0, wb1);
            WPAIR(sC, wc0, wc1);
            WPAIR(sD, wd0, wd1);

            #pragma unroll
            for (int j = 0; j < 4; j++) {
                __half2 t = __hmul2(H2AT(qa0, j), wa0);
                t = __hfma2(H2AT(qa1, j), wa1, t);
                t = __hfma2(H2AT(qb0, j), wb0, t);
                t = __hfma2(H2AT(qb1, j), wb1, t);
                t = __hfma2(H2AT(qc0, j), wc0, t);
                t = __hfma2(H2AT(qc1, j), wc1, t);
                t = __hfma2(H2AT(qd0, j), wd0, t);
                t = __hfma2(H2AT(qd1, j), wd1, t);
                const float2 v = __half22float2(t);
                accL[j] += v.x; accH[j] += v.y;
            }
        }
        #undef LOADQ
        #undef WPAIR
        #undef H2AT

        const float inv13 = 1.0f / 13.0f;
        #pragma unroll
        for (int j = 0; j < 4; j++)
            res[j] *= (accL[j] + accH[j]) * inv13;
    }

    float4 o;
    o.x = res[0]; o.y = res[1]; o.z = res[2]; o.w = res[3];
    ((float4*)out)[orig * 8 + cl] = o;
}

extern "C" void kernel_launch(void* const* d_in, const int* in_sizes, int n_in,
                              void* d_out, int out_size) {
    (void)in_sizes; (void)n_in; (void)out_size;
    const float* pts    = (const float*)d_in[0];
    const float* scales = (const float*)d_in[2];
    const float* p0     = (const float*)d_in[3];
    const float* p1     = (const float*)d_in[4];
    const float* p2     = (const float*)d_in[5];
    const float* aabb   = (const float*)d_in[6];
    float* out          = (float*)d_out;

    prep_kernel<<<768 + NPTS / 256, 256>>>(p0, p1, p2, pts);   // launch 1
    scan_kernel<<<1, 1024>>>();                                // launch 2
    scatter_kernel<<<NPTS / 256, 256>>>(pts, scales, aabb);    // launch 3
    sample_kernel<<<(NPTS * 8) / 256, 256>>>(out);             // launch 4 (ncu target)
}

// round 12
// speedup vs baseline: 1.0437x; 1.0194x over previous
#include <cuda_runtime.h>
#include <cuda_fp16.h>

#define RES   256
#define FEAT  32
#define NPTS  524288
#define NBA   32
#define NBINS (NBA * NBA * NBA)   // 32768

// Pair-interleaved fp16 planes: cell (y,x) -> 128B block of half2(f(x,c), f(x+1,c))
__device__ __half2  g_pi[3][RES * RES * FEAT];   // 25 MB
__device__ unsigned g_binid[NPTS];
__device__ unsigned g_count[NBINS];              // zero-init; re-zeroed by scan
__device__ unsigned g_offset[NBINS];
__device__ float4   g_sdata[NPTS * 2];

// ---------------- plane interleave: (C,H,W) fp32 -> (H,W,C) half2 x-pairs ----------------
__global__ void interleave_kernel(const float* __restrict__ p0,
                                  const float* __restrict__ p1,
                                  const float* __restrict__ p2) {
    __shared__ float srow[FEAT][RES + 1];
    const float* src = (blockIdx.y == 0) ? p0 : (blockIdx.y == 1 ? p1 : p2);
    __half2* dst = g_pi[blockIdx.y];
    const int y = blockIdx.x;
    const int t = threadIdx.x;

    #pragma unroll
    for (int c = 0; c < FEAT; c++)
        srow[c][t] = src[c * (RES * RES) + y * RES + t];
    __syncthreads();

    #pragma unroll
    for (int i = t; i < RES * FEAT; i += 256) {
        const int x = i >> 5;
        const int c = i & 31;
        const float a = srow[c][x];
        const float b = srow[c][(x + 1 < RES) ? x + 1 : RES - 1];
        dst[(y * RES + x) * FEAT + c] = __floats2half2_rn(a, b);
    }
}

// ---------------- Morton counting sort ----------------
__device__ __forceinline__ unsigned spread3(unsigned v) {
    unsigned r = (v & 1u);
    r |= (v & 2u)  << 2;
    r |= (v & 4u)  << 4;
    r |= (v & 8u)  << 6;
    r |= (v & 16u) << 8;
    return r;
}

__global__ void bin_kernel(const float* __restrict__ pts) {
    int p = blockIdx.x * blockDim.x + threadIdx.x;
    if (p >= NPTS) return;
    const float x = pts[p * 3 + 0];
    const float y = pts[p * 3 + 1];
    const float z = pts[p * 3 + 2];
    const float k = (float)NBA / 2.6f;
    int ix = min(NBA - 1, max(0, (int)((x + 1.3f) * k)));
    int iy = min(NBA - 1, max(0, (int)((y + 1.3f) * k)));
    int iz = min(NBA - 1, max(0, (int)((z + 1.3f) * k)));
    unsigned code = spread3(ix) | (spread3(iy) << 1) | (spread3(iz) << 2);
    g_binid[p] = code;
    atomicAdd(&g_count[code], 1u);
}

// single-block exclusive scan of g_count -> g_offset (absolute); re-zeroes g_count
__global__ void scan_kernel() {
    __shared__ unsigned sh[1024];
    const int t = threadIdx.x;        // 1024 threads, 32 bins each
    unsigned local[32];
    unsigned sum = 0;
    #pragma unroll
    for (int k = 0; k < 32; k++) {
        const int idx = t * 32 + k;
        const unsigned v = g_count[idx];
        g_count[idx] = 0;
        local[k] = sum;
        sum += v;
    }
    sh[t] = sum;
    __syncthreads();
    #pragma unroll
    for (int d = 1; d < 1024; d <<= 1) {
        unsigned add = (t >= d) ? sh[t - d] : 0u;
        __syncthreads();
        sh[t] += add;
        __syncthreads();
    }
    const unsigned base = sh[t] - sum;
    #pragma unroll
    for (int k = 0; k < 32; k++)
        g_offset[t * 32 + k] = base + local[k];
}

__global__ void scatter_kernel(const float* __restrict__ pts,
                               const float* __restrict__ scales,
                               const float* __restrict__ aabb) {
    int p = blockIdx.x * blockDim.x + threadIdx.x;
    if (p >= NPTS) return;
    const unsigned bin = g_binid[p];
    const unsigned pos = atomicAdd(&g_offset[bin], 1u);

    const float a00 = aabb[0], a01 = aabb[1], a02 = aabb[2];
    const float a10 = aabb[3], a11 = aabb[4], a12 = aabb[5];
    const float n0 = (pts[p * 3 + 0] - a00) * (2.0f / (a10 - a00)) - 1.0f;
    const float n1 = (pts[p * 3 + 1] - a01) * (2.0f / (a11 - a01)) - 1.0f;
    const float n2 = (pts[p * 3 + 2] - a02) * (2.0f / (a12 - a02)) - 1.0f;

    g_sdata[pos * 2 + 0] = make_float4(n0, n1, n2, scales[p * 3 + 0]);
    g_sdata[pos * 2 + 1] = make_float4(scales[p * 3 + 1], scales[p * 3 + 2],
                                       __int_as_float(p), 0.0f);
}

// ---------------- main sampling kernel ----------------
__host__ __device__ constexpr int SIX(int s) {
    constexpr int t[13] = {2, 0, 1, 3, 4, 2, 2, 2, 2, 3, 3, 1, 1};
    return t[s];
}
__host__ __device__ constexpr int SIY(int s) {
    constexpr int t[13] = {2, 2, 2, 2, 2, 0, 1, 3, 4, 3, 1, 3, 1};
    return t[s];
}

// 8 lanes per point (4 channels each), 4 sorted points per warp.
// Weights as products of per-axis fp16 factors: 2 HMUL2 per sample.
__global__ void __launch_bounds__(256, 3) sample_kernel(float* __restrict__ out)
{
    const int tid  = blockIdx.x * blockDim.x + threadIdx.x;
    const int lane = tid & 31;
    const int grp  = lane >> 3;
    const int cl   = lane & 7;
    const int i    = (tid >> 5) * 4 + grp;

    const float4 d0 = g_sdata[i * 2 + 0];
    const float4 d1 = g_sdata[i * 2 + 1];
    const float n[3] = { d0.x, d0.y, d0.z };
    const float s[3] = { d0.w, d1.x, d1.y };
    const int   orig = __float_as_int(d1.z);

    const int qidx[3] = {0, 0, 1};
    const int ridx[3] = {1, 2, 2};

    float res[4];
    #pragma unroll
    for (int j = 0; j < 4; j++) res[j] = 1.0f;

    #pragma unroll
    for (int pl = 0; pl < 3; pl++) {
        const float bx = n[qidx[pl]];
        const float by = n[ridx[pl]];
        const float sx = s[qidx[pl]];
        const float sy = s[ridx[pl]];
        const uint4* __restrict__ base = ((const uint4*)g_pi[pl]) + cl;

        // per-axis: offsets + fp16 weight factors
        __half2 hx[5];    // (1-wx, wx)
        __half2 hyl[5];   // (1-wy, 1-wy)
        __half2 hyh[5];   // (wy, wy)
        int xo[5], yo0[5], yo1[5];
        #pragma unroll
        for (int k = 0; k < 5; k++) {
            const float m = (float)(k - 2) * 0.5f;

            const float gx = fmaf(sx, m, bx);
            float cx = fminf(fmaxf(fmaf(gx, 127.5f, 127.5f), 0.0f), 255.0f);
            const float x0f = floorf(cx);
            const float wx = cx - x0f;
            hx[k] = __floats2half2_rn(1.0f - wx, wx);
            xo[k] = (int)x0f * 8;

            const float gy = fmaf(sy, m, by);
            float cy = fminf(fmaxf(fmaf(gy, 127.5f, 127.5f), 0.0f), 255.0f);
            const float y0f = floorf(cy);
            const float wy = cy - y0f;
            hyl[k] = __float2half2_rn(1.0f - wy);
            hyh[k] = __float2half2_rn(wy);
            const int y0 = (int)y0f;
            yo0[k] = y0 * (RES * 8);
            yo1[k] = min(y0 + 1, RES - 1) * (RES * 8);
        }

        float accL[4], accH[4];
        #pragma unroll
        for (int j = 0; j < 4; j++) { accL[j] = 0.0f; accH[j] = 0.0f; }

        #define LOADQ(smp, Q0, Q1)                                            \
            { const int ax_ = SIX(smp); const int ay_ = SIY(smp);             \
              Q0 = base[yo0[ay_] + xo[ax_]];                                  \
              Q1 = base[yo1[ay_] + xo[ax_]]; }

        #define WPAIR(smp, WP0, WP1)                                          \
            { const __half2 hx_ = hx[SIX(smp)];                               \
              WP0 = __hmul2(hx_, hyl[SIY(smp)]);                              \
              WP1 = __hmul2(hx_, hyh[SIY(smp)]); }

        #define H2AT(Q, j) (*reinterpret_cast<const __half2*>(&(&(Q).x)[j]))

        // sample 0 alone, flushed
        {
            uint4 q0, q1;
            LOADQ(0, q0, q1);
            __half2 wp0, wp1;
            WPAIR(0, wp0, wp1);
            #pragma unroll
            for (int j = 0; j < 4; j++) {
                __half2 t = __hmul2(H2AT(q0, j), wp0);
                t = __hfma2(H2AT(q1, j), wp1, t);
                const float2 v = __half22float2(t);
                accL[j] += v.x; accH[j] += v.y;
            }
        }

        // 3 groups of 4 samples: fp16 chain (8 terms), single flush
        #pragma unroll
        for (int g = 0; g < 3; g++) {
            const int sA = 1 + g * 4, sB = 2 + g * 4, sC = 3 + g * 4, sD = 4 + g * 4;
            uint4 qa0, qa1, qb0, qb1, qc0, qc1, qd0, qd1;
            LOADQ(sA, qa0, qa1);
            LOADQ(sB, qb0, qb1);
            LOADQ(sC, qc0, qc1);
            LOADQ(sD, qd0, qd1);

            __half2 wa0, wa1, wb0, wb1, wc0, wc1, wd0, wd1;
            WPAIR(sA, wa0, wa1);
            WPAIR(sB, wb0, wb1);
            WPAIR(sC, wc0, wc1);
            WPAIR(sD, wd0, wd1);

            #pragma unroll
            for (int j = 0; j < 4; j++) {
                __half2 t = __hmul2(H2AT(qa0, j), wa0);
                t = __hfma2(H2AT(qa1, j), wa1, t);
                t = __hfma2(H2AT(qb0, j), wb0, t);
                t = __hfma2(H2AT(qb1, j), wb1, t);
                t = __hfma2(H2AT(qc0, j), wc0, t);
                t = __hfma2(H2AT(qc1, j), wc1, t);
                t = __hfma2(H2AT(qd0, j), wd0, t);
                t = __hfma2(H2AT(qd1, j), wd1, t);
                const float2 v = __half22float2(t);
                accL[j] += v.x; accH[j] += v.y;
            }
        }
        #undef LOADQ
        #undef WPAIR
        #undef H2AT

        const float inv13 = 1.0f / 13.0f;
        #pragma unroll
        for (int j = 0; j < 4; j++)
            res[j] *= (accL[j] + accH[j]) * inv13;
    }

    float4 o;
    o.x = res[0]; o.y = res[1]; o.z = res[2]; o.w = res[3];
    ((float4*)out)[orig * 8 + cl] = o;
}

extern "C" void kernel_launch(void* const* d_in, const int* in_sizes, int n_in,
                              void* d_out, int out_size) {
    (void)in_sizes; (void)n_in; (void)out_size;
    const float* pts    = (const float*)d_in[0];
    const float* scales = (const float*)d_in[2];
    const float* p0     = (const float*)d_in[3];
    const float* p1     = (const float*)d_in[4];
    const float* p2     = (const float*)d_in[5];
    const float* aabb   = (const float*)d_in[6];
    float* out          = (float*)d_out;

    interleave_kernel<<<dim3(RES, 3), 256>>>(p0, p1, p2);
    bin_kernel<<<NPTS / 256, 256>>>(pts);
    scan_kernel<<<1, 1024>>>();
    scatter_kernel<<<NPTS / 256, 256>>>(pts, scales, aabb);
    sample_kernel<<<(NPTS * 8) / 256, 256>>>(out);
}

// round 13
// speedup vs baseline: 1.2521x; 1.1996x over previous
#include <cuda_runtime.h>
#include <cuda_fp16.h>

#define RES   256
#define FEAT  32
#define NPTS  524288
#define NBA   32
#define NBINS (NBA * NBA * NBA)   // 32768

// Pair-interleaved fp16 planes: cell (y,x) -> 128B block of half2(f(x,c), f(x+1,c))
__device__ __half2  g_pi[3][RES * RES * FEAT];   // 25 MB
__device__ unsigned g_binid[NPTS];
__device__ unsigned g_count[NBINS];              // zero-init; re-zeroed by scan
__device__ unsigned g_offset[NBINS];
__device__ unsigned g_bsum[32];
__device__ float4   g_sdata[NPTS * 2];           // prescaled: (bx,by,bz,sx)*127.5 (+127.5 for b)

// packed fp32 pair add (sm_103a f32x2 pipe)
__device__ __forceinline__ void addf32x2(float2& a, const float2 b) {
    unsigned long long ua = *reinterpret_cast<const unsigned long long*>(&a);
    unsigned long long ub = *reinterpret_cast<const unsigned long long*>(&b);
    unsigned long long uo;
    asm("add.rn.f32x2 %0, %1, %2;" : "=l"(uo) : "l"(ua), "l"(ub));
    a = *reinterpret_cast<float2*>(&uo);
}

// ---------------- plane interleave: (C,H,W) fp32 -> (H,W,C) half2 x-pairs ----------------
__global__ void interleave_kernel(const float* __restrict__ p0,
                                  const float* __restrict__ p1,
                                  const float* __restrict__ p2) {
    __shared__ float srow[FEAT][RES + 1];
    const float* src = (blockIdx.y == 0) ? p0 : (blockIdx.y == 1 ? p1 : p2);
    __half2* dst = g_pi[blockIdx.y];
    const int y = blockIdx.x;
    const int t = threadIdx.x;

    #pragma unroll
    for (int c = 0; c < FEAT; c++)
        srow[c][t] = src[c * (RES * RES) + y * RES + t];
    __syncthreads();

    #pragma unroll
    for (int i = t; i < RES * FEAT; i += 256) {
        const int x = i >> 5;
        const int c = i & 31;
        const float a = srow[c][x];
        const float b = srow[c][(x + 1 < RES) ? x + 1 : RES - 1];
        dst[(y * RES + x) * FEAT + c] = __floats2half2_rn(a, b);
    }
}

// ---------------- Morton counting sort ----------------
__device__ __forceinline__ unsigned spread3(unsigned v) {
    unsigned r = (v & 1u);
    r |= (v & 2u)  << 2;
    r |= (v & 4u)  << 4;
    r |= (v & 8u)  << 6;
    r |= (v & 16u) << 8;
    return r;
}

__global__ void bin_kernel(const float* __restrict__ pts) {
    int p = blockIdx.x * blockDim.x + threadIdx.x;
    if (p >= NPTS) return;
    const float x = pts[p * 3 + 0];
    const float y = pts[p * 3 + 1];
    const float z = pts[p * 3 + 2];
    const float k = (float)NBA / 2.6f;
    int ix = min(NBA - 1, max(0, (int)((x + 1.3f) * k)));
    int iy = min(NBA - 1, max(0, (int)((y + 1.3f) * k)));
    int iz = min(NBA - 1, max(0, (int)((z + 1.3f) * k)));
    unsigned code = spread3(ix) | (spread3(iy) << 1) | (spread3(iz) << 2);
    g_binid[p] = code;
    atomicAdd(&g_count[code], 1u);
}

// reads g_count, writes local-exclusive scan to g_offset, zeroes g_count
__global__ void scan_block_kernel() {
    __shared__ unsigned sh[1024];
    const int t = threadIdx.x;
    const int i = blockIdx.x * 1024 + t;
    const unsigned v = g_count[i];
    g_count[i] = 0;
    sh[t] = v;
    __syncthreads();
    #pragma unroll
    for (int d = 1; d < 1024; d <<= 1) {
        unsigned add = (t >= d) ? sh[t - d] : 0u;
        __syncthreads();
        sh[t] += add;
        __syncthreads();
    }
    g_offset[i] = sh[t] - v;
    if (t == 1023) g_bsum[blockIdx.x] = sh[t];
}

__global__ void scan_top_kernel() {
    const int t = threadIdx.x;   // 32
    const unsigned v = g_bsum[t];
    unsigned x = v;
    #pragma unroll
    for (int d = 1; d < 32; d <<= 1) {
        unsigned y = __shfl_up_sync(0xffffffffu, x, d);
        if (t >= d) x += y;
    }
    g_bsum[t] = x - v;
}

__global__ void scatter_kernel(const float* __restrict__ pts,
                               const float* __restrict__ scales,
                               const float* __restrict__ aabb) {
    int p = blockIdx.x * blockDim.x + threadIdx.x;
    if (p >= NPTS) return;
    const unsigned bin = g_binid[p];
    const unsigned pos = g_bsum[bin >> 10] + atomicAdd(&g_offset[bin], 1u);

    const float a00 = aabb[0], a01 = aabb[1], a02 = aabb[2];
    const float a10 = aabb[3], a11 = aabb[4], a12 = aabb[5];
    const float n0 = (pts[p * 3 + 0] - a00) * (2.0f / (a10 - a00)) - 1.0f;
    const float n1 = (pts[p * 3 + 1] - a01) * (2.0f / (a11 - a01)) - 1.0f;
    const float n2 = (pts[p * 3 + 2] - a02) * (2.0f / (a12 - a02)) - 1.0f;

    // prescale to pixel space: b = n*127.5 + 127.5, s = scale*127.5
    g_sdata[pos * 2 + 0] = make_float4(fmaf(n0, 127.5f, 127.5f),
                                       fmaf(n1, 127.5f, 127.5f),
                                       fmaf(n2, 127.5f, 127.5f),
                                       scales[p * 3 + 0] * 127.5f);
    g_sdata[pos * 2 + 1] = make_float4(scales[p * 3 + 1] * 127.5f,
                                       scales[p * 3 + 2] * 127.5f,
                                       __int_as_float(p), 0.0f);
}

// ---------------- main sampling kernel ----------------
__host__ __device__ constexpr int SIX(int s) {
    constexpr int t[13] = {2, 0, 1, 3, 4, 2, 2, 2, 2, 3, 3, 1, 1};
    return t[s];
}
__host__ __device__ constexpr int SIY(int s) {
    constexpr int t[13] = {2, 2, 2, 2, 2, 0, 1, 3, 4, 3, 1, 3, 1};
    return t[s];
}

// 8 lanes per point (4 channels each), 4 sorted points per warp.
// Prescaled coords: 1 fma per axis per k. No clamps (coords in [6.4, 248.6]).
__global__ void __launch_bounds__(256, 3) sample_kernel(float* __restrict__ out)
{
    const int tid  = blockIdx.x * blockDim.x + threadIdx.x;
    const int lane = tid & 31;
    const int grp  = lane >> 3;
    const int cl   = lane & 7;
    const int i    = (tid >> 5) * 4 + grp;

    const float4 d0 = g_sdata[i * 2 + 0];
    const float4 d1 = g_sdata[i * 2 + 1];
    const float n[3] = { d0.x, d0.y, d0.z };   // prescaled pixel-space centers
    const float s[3] = { d0.w, d1.x, d1.y };   // prescaled pixel-space scales
    const int   orig = __float_as_int(d1.z);

    const int qidx[3] = {0, 0, 1};
    const int ridx[3] = {1, 2, 2};

    float res[4];
    #pragma unroll
    for (int j = 0; j < 4; j++) res[j] = 1.0f;

    #pragma unroll
    for (int pl = 0; pl < 3; pl++) {
        const float bx = n[qidx[pl]];
        const float by = n[ridx[pl]];
        const float sx = s[qidx[pl]];
        const float sy = s[ridx[pl]];
        const uint4* __restrict__ base = ((const uint4*)g_pi[pl]) + cl;

        float xw[5], yw[5];
        int   xo[5], yo0[5];
        #pragma unroll
        for (int k = 0; k < 5; k++) {
            const float m = (float)(k - 2) * 0.5f;

            const float cx  = fmaf(sx, m, bx);        // in [6.4, 248.6]
            const float x0f = floorf(cx);
            xw[k] = cx - x0f;
            xo[k] = (int)x0f * 8;

            const float cy  = fmaf(sy, m, by);
            const float y0f = floorf(cy);
            yw[k] = cy - y0f;
            yo0[k] = (int)y0f * (RES * 8);
        }

        float2 acc[4];
        #pragma unroll
        for (int j = 0; j < 4; j++) { acc[j].x = 0.0f; acc[j].y = 0.0f; }

        #define LOADQ(smp, Q0, Q1)                                            \
            { const int o_ = yo0[SIY(smp)] + xo[SIX(smp)];                    \
              Q0 = base[o_];                                                  \
              Q1 = base[o_ + RES * 8]; }

        #define WPAIR(smp, WP0, WP1)                                          \
            { const float wx_ = xw[SIX(smp)];                                 \
              const float wy_ = yw[SIY(smp)];                                 \
              const float w11_ = wx_ * wy_;                                   \
              WP0 = __floats2half2_rn(1.0f - wx_ - (wy_ - w11_), wx_ - w11_); \
              WP1 = __floats2half2_rn(wy_ - w11_, w11_); }

        #define H2AT(Q, j) (*reinterpret_cast<const __half2*>(&(&(Q).x)[j]))

        // sample 0 alone, flushed
        {
            uint4 q0, q1;
            LOADQ(0, q0, q1);
            __half2 wp0, wp1;
            WPAIR(0, wp0, wp1);
            #pragma unroll
            for (int j = 0; j < 4; j++) {
                __half2 t = __hmul2(H2AT(q0, j), wp0);
                t = __hfma2(H2AT(q1, j), wp1, t);
                addf32x2(acc[j], __half22float2(t));
            }
        }

        // 3 groups of 4 samples: fp16 chain (8 terms), single packed flush
        #pragma unroll
        for (int g = 0; g < 3; g++) {
            const int sA = 1 + g * 4, sB = 2 + g * 4, sC = 3 + g * 4, sD = 4 + g * 4;
            uint4 qa0, qa1, qb0, qb1, qc0, qc1, qd0, qd1;
            LOADQ(sA, qa0, qa1);
            LOADQ(sB, qb0, qb1);
            LOADQ(sC, qc0, qc1);
            LOADQ(sD, qd0, qd1);

            __half2 wa0, wa1, wb0, wb1, wc0, wc1, wd0, wd1;
            WPAIR(sA, wa0, wa1);
            WPAIR(sB, wb0, wb1);
            WPAIR(sC, wc0, wc1);
            WPAIR(sD, wd0, wd1);

            #pragma unroll
            for (int j = 0; j < 4; j++) {
                __half2 t = __hmul2(H2AT(qa0, j), wa0);
                t = __hfma2(H2AT(qa1, j), wa1, t);
                t = __hfma2(H2AT(qb0, j), wb0, t);
                t = __hfma2(H2AT(qb1, j), wb1, t);
                t = __hfma2(H2AT(qc0, j), wc0, t);
                t = __hfma2(H2AT(qc1, j), wc1, t);
                t = __hfma2(H2AT(qd0, j), wd0, t);
                t = __hfma2(H2AT(qd1, j), wd1, t);
                addf32x2(acc[j], __half22float2(t));
            }
        }
        #undef LOADQ
        #undef WPAIR
        #undef H2AT

        const float inv13 = 1.0f / 13.0f;
        #pragma unroll
        for (int j = 0; j < 4; j++)
            res[j] *= (acc[j].x + acc[j].y) * inv13;
    }

    float4 o;
    o.x = res[0]; o.y = res[1]; o.z = res[2]; o.w = res[3];
    ((float4*)out)[orig * 8 + cl] = o;
}

extern "C" void kernel_launch(void* const* d_in, const int* in_sizes, int n_in,
                              void* d_out, int out_size) {
    (void)in_sizes; (void)n_in; (void)out_size;
    const float* pts    = (const float*)d_in[0];
    const float* scales = (const float*)d_in[2];
    const float* p0     = (const float*)d_in[3];
    const float* p1     = (const float*)d_in[4];
    const float* p2     = (const float*)d_in[5];
    const float* aabb   = (const float*)d_in[6];
    float* out          = (float*)d_out;

    interleave_kernel<<<dim3(RES, 3), 256>>>(p0, p1, p2);
    bin_kernel<<<NPTS / 256, 256>>>(pts);
    scan_block_kernel<<<NBINS / 1024, 1024>>>();
    scan_top_kernel<<<1, 32>>>();
    scatter_kernel<<<NPTS / 256, 256>>>(pts, scales, aabb);
    sample_kernel<<<(NPTS * 8) / 256, 256>>>(out);
}